// round 4
// baseline (speedup 1.0000x reference)
#include <cuda_runtime.h>
#include <cuda_bf16.h>
#include <cstdint>

#define B_N   65536
#define IN_N  512
#define H_N   1024
#define STEPS 10
#define BETA  0.9f
#define THR   1.0f

// ---------------- static scratch ----------------
__device__ float    g_cur1[(size_t)B_N * H_N];            // 268 MB
__device__ unsigned g_s1bits[STEPS][H_N / 32][B_N];       // 84 MB
__device__ float    g_cur2[STEPS][(size_t)B_N * H_N];     // 2.68 GB
__device__ char     g_W2q[4][H_N][H_N];                   // 4 MB: int8 digit planes [p][n][k], p0=MSD

// ---------------- K0: exact 4-digit radix-256 split of W2 at scale 2^30 ----------------
__global__ __launch_bounds__(256) void k0_split(const float* __restrict__ W2) {
    int i = blockIdx.x * 256 + threadIdx.x;       // over 1024*1024, W2[k][n]
    int k = i >> 10, n = i & (H_N - 1);
    float w = W2[i];
    int q  = __float2int_rn(w * 1073741824.0f);   // * 2^30, |q| < 2^28
    int d0 = (int)(signed char)(q & 0xFF);
    int q1 = (q - d0) >> 8;
    int d1 = (int)(signed char)(q1 & 0xFF);
    int q2 = (q1 - d1) >> 8;
    int d2 = (int)(signed char)(q2 & 0xFF);
    int d3 = (q2 - d2) >> 8;                      // |d3| <= ~11
    g_W2q[0][n][k] = (char)d3;
    g_W2q[1][n][k] = (char)d2;
    g_W2q[2][n][k] = (char)d1;
    g_W2q[3][n][k] = (char)d0;
}

// ---------------- K1: cur1 = x @ W1 + b1 (fp32 SIMT, identical to passing R1) ----------------
__global__ __launch_bounds__(256) void k1_gemm(const float* __restrict__ X,
                                               const float* __restrict__ W1,
                                               const float* __restrict__ b1) {
    __shared__ float As[16][128];
    __shared__ float Bs[16][128];
    const int tid = threadIdx.x;
    const int tx = tid & 15, ty = tid >> 4;
    const int m0 = blockIdx.y * 128;
    const int n0 = blockIdx.x * 128;

    float acc[8][8];
#pragma unroll
    for (int i = 0; i < 8; i++)
#pragma unroll
        for (int j = 0; j < 8; j++) acc[i][j] = 0.f;

    for (int kc = 0; kc < IN_N; kc += 16) {
        float4 av[2], bv[2];
#pragma unroll
        for (int l = 0; l < 2; l++) {
            int f = tid + l * 256;
            int row = f >> 2, kq = (f & 3) * 4;
            av[l] = *(const float4*)&X[(size_t)(m0 + row) * IN_N + kc + kq];
            int kr = f >> 5, c4 = (f & 31) * 4;
            bv[l] = *(const float4*)&W1[(size_t)(kc + kr) * H_N + n0 + c4];
        }
        __syncthreads();
#pragma unroll
        for (int l = 0; l < 2; l++) {
            int f = tid + l * 256;
            int row = f >> 2, kq = (f & 3) * 4;
            As[kq + 0][row] = av[l].x; As[kq + 1][row] = av[l].y;
            As[kq + 2][row] = av[l].z; As[kq + 3][row] = av[l].w;
            int kr = f >> 5, c4 = (f & 31) * 4;
            *(float4*)&Bs[kr][c4] = bv[l];
        }
        __syncthreads();
#pragma unroll
        for (int kk = 0; kk < 16; kk++) {
            float a[8], bb[8];
            *(float4*)&a[0]  = *(float4*)&As[kk][ty * 8];
            *(float4*)&a[4]  = *(float4*)&As[kk][ty * 8 + 4];
            *(float4*)&bb[0] = *(float4*)&Bs[kk][tx * 8];
            *(float4*)&bb[4] = *(float4*)&Bs[kk][tx * 8 + 4];
#pragma unroll
            for (int i = 0; i < 8; i++)
#pragma unroll
                for (int j = 0; j < 8; j++) acc[i][j] += a[i] * bb[j];
        }
    }

    float bias[8];
#pragma unroll
    for (int j = 0; j < 8; j++) bias[j] = b1[n0 + tx * 8 + j];
#pragma unroll
    for (int i = 0; i < 8; i++) {
        int row = m0 + ty * 8 + i;
        float4 o0, o1;
        o0.x = acc[i][0] + bias[0]; o0.y = acc[i][1] + bias[1];
        o0.z = acc[i][2] + bias[2]; o0.w = acc[i][3] + bias[3];
        o1.x = acc[i][4] + bias[4]; o1.y = acc[i][5] + bias[5];
        o1.z = acc[i][6] + bias[6]; o1.w = acc[i][7] + bias[7];
        *(float4*)&g_cur1[(size_t)row * H_N + n0 + tx * 8]     = o0;
        *(float4*)&g_cur1[(size_t)row * H_N + n0 + tx * 8 + 4] = o1;
    }
}

// ---------------- K2: layer-1 LIF -> spike bitplanes ----------------
__global__ __launch_bounds__(256) void k2_s1gen() {
    const int W    = blockIdx.x * 8 + (threadIdx.x >> 5);
    const int lane = threadIdx.x & 31;
    const int b = W & (B_N - 1);
    const int j = W >> 16;
    const float c = g_cur1[(size_t)b * H_N + j * 32 + lane];
    float m = 0.f;
#pragma unroll
    for (int t = 0; t < STEPS; t++) {
        float r = (m > THR) ? THR : 0.f;
        m = BETA * m + c - r;
        unsigned bal = __ballot_sync(0xFFFFFFFFu, m > THR);
        if (lane == 0) g_s1bits[t][j][b] = bal;
    }
}

// ---------------- K3: persistent-stripe 4-plane int8 IMMA GEMM (exact to 2^-30) ------------
// CTA owns a 32-col stripe of all 4 digit planes in smem (loaded once, k-permuted so each
// (b0,b1) fragment pair is one LDS.64), sweeps (t, m-tile) tasks: M=256, N=32, K=1024.
// 8 warps: warp w owns rows w*32..w*32+31, all 32 cols.

#define SB_PITCH 1056                    // 1024 + 32: conflict-free LDS.64 pattern
#define SB_PLANE (32 * SB_PITCH)
#define SB_TOTAL (4 * SB_PLANE)          // 135168 bytes
#define NWORK 4                          // CTAs per stripe; 32*4 = 128 CTAs
#define NTASK ((B_N / 256) * STEPS)      // 2560

__device__ __forceinline__ unsigned bexp(unsigned nib) {
    return (nib & 0xFu) * 0x00204081u & 0x01010101u;   // 4 bits -> 4 bytes of 0/1
}

__device__ __forceinline__ void imma(int* c, const unsigned* a, unsigned b0, unsigned b1) {
    asm volatile(
        "mma.sync.aligned.m16n8k32.row.col.s32.s8.s8.s32 "
        "{%0,%1,%2,%3}, {%4,%5,%6,%7}, {%8,%9}, {%0,%1,%2,%3};"
        : "+r"(c[0]), "+r"(c[1]), "+r"(c[2]), "+r"(c[3])
        : "r"(a[0]), "r"(a[1]), "r"(a[2]), "r"(a[3]), "r"(b0), "r"(b1));
}

__global__ __launch_bounds__(256, 1) void k3_imma() {
    extern __shared__ char sB[];
    const int tid  = threadIdx.x;
    const int lane = tid & 31, wid = tid >> 5;
    const int n0 = blockIdx.x * 32;

    // Stage stripe (once), permuting k within each 32-byte chunk:
    //   pos(g*8 + hi*4 + b) = k (hi*16 + g*4 + b)  => LDS.64 at g*8 yields (b0,b1)
    for (int i = tid; i < 4 * 32 * 64; i += 256) {
        int p = i >> 11, rem = i & 2047;
        int n = rem >> 6, c16 = rem & 63;            // 16B chunk: k = c16*16..+15
        uint4 v = *(const uint4*)&g_W2q[p][n0 + n][c16 * 16];
        char* dst = sB + p * SB_PLANE + n * SB_PITCH + (c16 >> 1) * 32 + (c16 & 1) * 4;
        *(unsigned*)(dst + 0)  = v.x;                // k-group g=0
        *(unsigned*)(dst + 8)  = v.y;                // g=1
        *(unsigned*)(dst + 16) = v.z;                // g=2
        *(unsigned*)(dst + 24) = v.w;                // g=3
    }
    __syncthreads();

    const int rsub = lane >> 2;                      // row/col group 0..7
    const int kq   = (lane & 3) * 4;
    const char* bb = sB + rsub * SB_PITCH + (lane & 3) * 8;

    for (int task = blockIdx.y; task < NTASK; task += NWORK) {
        const int t  = task / (B_N / 256);
        const int m0 = (task % (B_N / 256)) * 256;
        const int rbase = m0 + wid * 32 + rsub;

        int acc[4][2][4][4];
#pragma unroll
        for (int p = 0; p < 4; p++)
#pragma unroll
            for (int mf = 0; mf < 2; mf++)
#pragma unroll
                for (int nf = 0; nf < 4; nf++)
#pragma unroll
                    for (int e = 0; e < 4; e++) acc[p][mf][nf][e] = 0;

        unsigned wc[4], wn[4];
#pragma unroll
        for (int r = 0; r < 4; r++)
            wc[r] = __ldg(&g_s1bits[t][0][rbase + r * 8]);

        for (int kc = 0; kc < 32; kc++) {
            if (kc < 31) {
#pragma unroll
                for (int r = 0; r < 4; r++)
                    wn[r] = __ldg(&g_s1bits[t][kc + 1][rbase + r * 8]);
            }
            unsigned a0[4], a1[4];
            a0[0] = bexp(wc[0] >> kq); a0[1] = bexp(wc[1] >> kq);
            a0[2] = bexp(wc[0] >> (16 + kq)); a0[3] = bexp(wc[1] >> (16 + kq));
            a1[0] = bexp(wc[2] >> kq); a1[1] = bexp(wc[3] >> kq);
            a1[2] = bexp(wc[2] >> (16 + kq)); a1[3] = bexp(wc[3] >> (16 + kq));
#pragma unroll
            for (int p = 0; p < 4; p++) {
#pragma unroll
                for (int nf = 0; nf < 4; nf++) {
                    uint2 b = *(const uint2*)(bb + p * SB_PLANE + nf * 8 * SB_PITCH + kc * 32);
                    imma(acc[p][0][nf], a0, b.x, b.y);
                    imma(acc[p][1][nf], a1, b.x, b.y);
                }
            }
#pragma unroll
            for (int r = 0; r < 4; r++) wc[r] = wn[r];
        }

        // epilogue: exact digit recombination -> correctly rounded fp32
        float* outp = g_cur2[t];
#pragma unroll
        for (int mf = 0; mf < 2; mf++) {
#pragma unroll
            for (int nf = 0; nf < 4; nf++) {
                float f[4];
#pragma unroll
                for (int e = 0; e < 4; e++) {
                    long long v = ((long long)acc[0][mf][nf][e] << 24)
                                + ((long long)acc[1][mf][nf][e] << 16)
                                + ((long long)acc[2][mf][nf][e] << 8)
                                +  (long long)acc[3][mf][nf][e];
                    f[e] = (float)((double)v * (1.0 / 1073741824.0));
                }
                int row = m0 + wid * 32 + mf * 16 + rsub;
                int col = n0 + nf * 8 + (lane & 3) * 2;
                *(float2*)&outp[(size_t)row * H_N + col]       = make_float2(f[0], f[1]);
                *(float2*)&outp[(size_t)(row + 8) * H_N + col] = make_float2(f[2], f[3]);
            }
        }
    }
}

// ---------------- K4: all 10 steps fused; m2/mo in registers ----------------
__global__ __launch_bounds__(256) void k4_all(const float* __restrict__ Wo,
                                              const float* __restrict__ b2,
                                              const float* __restrict__ bo,
                                              float* __restrict__ out) {
    __shared__ float red[8];
    const int b = blockIdx.x, tid = threadIdx.x;
    const int wid = tid >> 5, lane = tid & 31;
    const size_t base = (size_t)b * H_N + tid * 4;

    const float4 bv = *(const float4*)&b2[tid * 4];
    const float4 wo = *(const float4*)&Wo[tid * 4];
    float4 m = make_float4(0.f, 0.f, 0.f, 0.f);
    float mo = 0.f, a = 0.f;
    const float bo0 = bo[0];

    for (int t = 0; t < STEPS; t++) {
        float4 c = *(const float4*)&g_cur2[t][base];
        c.x += bv.x; c.y += bv.y; c.z += bv.z; c.w += bv.w;

        float p = 0.f, r;
        r = (m.x > THR) ? THR : 0.f; m.x = BETA * m.x + c.x - r; if (m.x > THR) p += wo.x;
        r = (m.y > THR) ? THR : 0.f; m.y = BETA * m.y + c.y - r; if (m.y > THR) p += wo.y;
        r = (m.z > THR) ? THR : 0.f; m.z = BETA * m.z + c.z - r; if (m.z > THR) p += wo.z;
        r = (m.w > THR) ? THR : 0.f; m.w = BETA * m.w + c.w - r; if (m.w > THR) p += wo.w;

#pragma unroll
        for (int o = 16; o; o >>= 1) p += __shfl_down_sync(0xFFFFFFFFu, p, o);
        if (lane == 0) red[wid] = p;
        __syncthreads();
        if (tid == 0) {
            float tot = bo0;
#pragma unroll
            for (int w = 0; w < 8; w++) tot += red[w];
            float ro = (mo > THR) ? THR : 0.f;
            mo = BETA * mo + tot - ro;
            a += mo;
        }
        __syncthreads();
    }
    if (tid == 0) out[b] = a * (1.f / STEPS);
}

// ---------------- launcher ----------------
extern "C" void kernel_launch(void* const* d_in, const int* in_sizes, int n_in,
                              void* d_out, int out_size) {
    const float* x  = (const float*)d_in[0];
    const float* W1 = (const float*)d_in[1];
    const float* b1 = (const float*)d_in[2];
    const float* W2 = (const float*)d_in[3];
    const float* b2 = (const float*)d_in[4];
    const float* Wo = (const float*)d_in[5];
    const float* bo = (const float*)d_in[6];
    float* out = (float*)d_out;

    cudaFuncSetAttribute(k3_imma, cudaFuncAttributeMaxDynamicSharedMemorySize, SB_TOTAL);

    k0_split<<<(H_N * H_N) / 256, 256>>>(W2);
    k1_gemm<<<dim3(H_N / 128, B_N / 128), 256>>>(x, W1, b1);
    k2_s1gen<<<(B_N / 8) * (H_N / 32), 256>>>();
    k3_imma<<<dim3(H_N / 32, NWORK), 256, SB_TOTAL>>>();
    k4_all<<<B_N, 256>>>(Wo, b2, bo, out);
}